// round 1
// baseline (speedup 1.0000x reference)
#include <cuda_runtime.h>

// Problem constants (match reference)
#define BSZ 8
#define T 4096
#define DM 1024
#define NCH 64               // number of time chunks
#define CHL 64               // chunk length = T / NCH
#define TGRP 16              // timesteps batched per LN reduction round
#define LN_EPS 1e-5f

// Scratch (no cudaMalloc allowed) — per-chunk local end states and start states
__device__ float g_hlocal[BSZ * NCH * DM];
__device__ float g_hstart[BSZ * NCH * DM];

// ---------------------------------------------------------------------------
// Pass 1: per (batch b, chunk c), compute h_local = scan of chunk with h0 = 0.
// One thread per channel d; warp covers 32 contiguous channels -> coalesced.
// ---------------------------------------------------------------------------
__global__ void __launch_bounds__(DM) ssm_pass1(
    const float* __restrict__ x,
    const float* __restrict__ A,
    const float* __restrict__ B)
{
    const int d = threadIdx.x;
    const int c = blockIdx.x;
    const int b = blockIdx.y;

    const float a  = A[d];
    const float bb = B[d];

    const float* __restrict__ xp =
        x + ((size_t)b * T + (size_t)c * CHL) * DM + d;

    float h = 0.0f;
#pragma unroll 8
    for (int t = 0; t < CHL; ++t) {
        h = fmaf(a, h, bb * xp[(size_t)t * DM]);
    }
    g_hlocal[((b * NCH) + c) * DM + d] = h;
}

// ---------------------------------------------------------------------------
// Combine: serial prefix over chunk aggregates.
// h_start[b][c] = A^CHL * h_start[b][c-1] + h_local[b][c-1],  h_start[b][0]=0
// 8192 threads total; tiny (4 MB traffic).
// ---------------------------------------------------------------------------
__global__ void ssm_combine(const float* __restrict__ A)
{
    const int idx = blockIdx.x * blockDim.x + threadIdx.x;   // over BSZ*DM
    const int d = idx & (DM - 1);
    const int b = idx >> 10;                                  // / DM

    const float a = A[d];
    float aL = 1.0f;
#pragma unroll
    for (int i = 0; i < CHL; ++i) aL *= a;                    // A^CHL

    float carry = 0.0f;
#pragma unroll 4
    for (int c = 0; c < NCH; ++c) {
        const int o = (b * NCH + c) * DM + d;
        g_hstart[o] = carry;
        carry = fmaf(aL, carry, g_hlocal[o]);
    }
}

// ---------------------------------------------------------------------------
// Pass 2: recurrence with correct h_start + fused LayerNorm.
// Block = 1024 threads (one per channel). For each group of TGRP=16 rows:
//   - each thread computes y for its channel, warp-reduces sum/sumsq (partial
//     over 32 lanes), lane 0 publishes to smem
//   - one __syncthreads; warps 0..15 each finish one row's 32 partials,
//     publish mu / rsqrt(var+eps)
//   - one __syncthreads; all threads write normalized output (coalesced)
// 2 barriers per 16 rows instead of per row.
// ---------------------------------------------------------------------------
__global__ void __launch_bounds__(DM) ssm_pass2(
    const float* __restrict__ x,
    const float* __restrict__ A,
    const float* __restrict__ B,
    const float* __restrict__ C,
    const float* __restrict__ D,
    const float* __restrict__ gamma,
    const float* __restrict__ beta,
    float* __restrict__ out)
{
    __shared__ float s_sum[TGRP][33];   // padded to dodge bank conflicts
    __shared__ float s_sq [TGRP][33];
    __shared__ float s_mu [TGRP];
    __shared__ float s_rs [TGRP];

    const int d    = threadIdx.x;
    const int lane = d & 31;
    const int w    = d >> 5;
    const int c    = blockIdx.x;
    const int b    = blockIdx.y;

    const float a  = A[d];
    const float bb = B[d];
    const float cc = C[d];
    const float dd = D[d];
    const float g  = gamma[d];
    const float be = beta[d];

    float h = g_hstart[(b * NCH + c) * DM + d];

    const size_t base = ((size_t)b * T + (size_t)c * CHL) * DM + d;

    for (int grp = 0; grp < CHL / TGRP; ++grp) {
        float y[TGRP];

#pragma unroll
        for (int tt = 0; tt < TGRP; ++tt) {
            const float xv = x[base + (size_t)(grp * TGRP + tt) * DM];
            h = fmaf(a, h, bb * xv);
            const float yv = fmaf(cc, h, dd * xv);
            y[tt] = yv;

            // warp partial reduce (sum, sumsq) for this row
            float s = yv;
            float q = yv * yv;
#pragma unroll
            for (int o = 16; o > 0; o >>= 1) {
                s += __shfl_xor_sync(0xFFFFFFFFu, s, o);
                q += __shfl_xor_sync(0xFFFFFFFFu, q, o);
            }
            if (lane == 0) {
                s_sum[tt][w] = s;
                s_sq [tt][w] = q;
            }
        }

        __syncthreads();

        if (w < TGRP) {
            // warp w finishes row tt = w
            float s = s_sum[w][lane];
            float q = s_sq [w][lane];
#pragma unroll
            for (int o = 16; o > 0; o >>= 1) {
                s += __shfl_xor_sync(0xFFFFFFFFu, s, o);
                q += __shfl_xor_sync(0xFFFFFFFFu, q, o);
            }
            if (lane == 0) {
                const float mu  = s * (1.0f / DM);
                const float var = q * (1.0f / DM) - mu * mu;
                s_mu[w] = mu;
                s_rs[w] = rsqrtf(var + LN_EPS);
            }
        }

        __syncthreads();

#pragma unroll
        for (int tt = 0; tt < TGRP; ++tt) {
            out[base + (size_t)(grp * TGRP + tt) * DM] =
                fmaf((y[tt] - s_mu[tt]) * s_rs[tt], g, be);
        }
        // No extra barrier needed: next group's s_sum/s_sq writes don't alias
        // s_mu/s_rs reads, and the next __syncthreads orders the s_mu rewrite.
    }
}

// ---------------------------------------------------------------------------
// Launch
// Inputs (metadata order): x, A, B, C, D, gamma, beta. Output: float32.
// ---------------------------------------------------------------------------
extern "C" void kernel_launch(void* const* d_in, const int* in_sizes, int n_in,
                              void* d_out, int out_size)
{
    const float* x     = (const float*)d_in[0];
    const float* A     = (const float*)d_in[1];
    const float* B     = (const float*)d_in[2];
    const float* C     = (const float*)d_in[3];
    const float* D     = (const float*)d_in[4];
    const float* gamma = (const float*)d_in[5];
    const float* beta  = (const float*)d_in[6];
    float* out = (float*)d_out;

    dim3 grid(NCH, BSZ);

    ssm_pass1<<<grid, DM>>>(x, A, B);
    ssm_combine<<<(BSZ * DM) / 256, 256>>>(A);
    ssm_pass2<<<grid, DM>>>(x, A, B, C, D, gamma, beta, out);
}